// round 7
// baseline (speedup 1.0000x reference)
#include <cuda_runtime.h>
#include <cuda_bf16.h>
#include <float.h>

#define Bn 128
#define On 1024
#define In 1024
#define EPSc 1e-7f
#define L2E 1.4426950408889634f

#define ICK 32                 // i's per block
#define IBR 4                  // i's staged per barrier round
#define GB  8                  // b's per block (= warps)
#define NIB (In / ICK)         // 32 partial slabs

// Scratch (no allocs allowed)
__device__ float    g_c2_im[In * On];          // C^2, i-major [i][o]
__device__ unsigned g_min[In];                 // min over o of C^2[:,i]
__device__ float4   g_bi[Bn * In];             // per (b,i): {g^2, Bm=-smax*L2E, d, 0}
__device__ float    g_part[NIB * Bn * On];     // partial sums [iblk][b][o]

__device__ __forceinline__ float rsqrt_nr(float x) {
    float r;
    asm("rsqrt.approx.ftz.f32 %0, %1;" : "=f"(r) : "f"(x));
    float t = x * r;
    return r * fmaf(t * r, -0.5f, 1.5f);   // one Newton step
}

__device__ __forceinline__ float ex2(float x) {
    float r;
    asm("ex2.approx.ftz.f32 %0, %1;" : "=f"(r) : "f"(x));
    return r;
}

// ---------------- init per-i min to +inf ----------------
__global__ void kinit() {
    int i = blockIdx.x * 256 + threadIdx.x;
    if (i < In) g_min[i] = 0x7F800000u;
}

// ---------------- Kernel P: C^2 transpose (o-major -> i-major) + per-i min ----
__global__ void kprep(const float* __restrict__ ix, const float* __restrict__ iy,
                      const float* __restrict__ ox, const float* __restrict__ oy,
                      const float* __restrict__ la, const float* __restrict__ lm) {
    __shared__ float tile[32][33];
    int tx = threadIdx.x & 31;
    int ty = threadIdx.x >> 5;
    int ob  = (blockIdx.x & 31) * 32;   // o tile base
    int ibt = (blockIdx.x >> 5) * 32;   // i tile base

#pragma unroll
    for (int k = 0; k < 4; k++) {
        int o = ob + ty + k * 8;
        int idx = o * In + ibt + tx;    // coalesced over tx (consecutive i)
        float c = (ix[idx] / iy[idx] + la[idx]) * (1.0f + lm[idx]) - ox[idx] / oy[idx];
        tile[ty + k * 8][tx] = c * c;
    }
    __syncthreads();

#pragma unroll
    for (int k = 0; k < 4; k++) {
        int il = ty + k * 8;            // local i
        float v = tile[tx][il];         // stride-33 -> conflict-free
        g_c2_im[(ibt + il) * In + ob + tx] = v;   // coalesced over tx (consecutive o)
        float mn = v;
#pragma unroll
        for (int s = 16; s; s >>= 1) mn = fminf(mn, __shfl_xor_sync(0xffffffffu, mn, s));
        if (tx == 0) atomicMin(&g_min[ibt + il], __float_as_uint(mn));
    }
}

// ---------------- Kernel G: per-(b,i) scalars {g^2, Bm, d} ----------------
__global__ void kg(const float* __restrict__ data) {
    int idx = blockIdx.x * 256 + threadIdx.x;   // b*In + i
    int i = idx & (In - 1);
    float d = data[idx];
    float g = 1.0f / (1.0f + __expf(-d));
    float g2 = g * g;
    float m2 = __uint_as_float(g_min[i]);
    float smax = rsqrt_nr(fmaf(m2, g2, EPSc));
    g_bi[idx] = make_float4(g2, -smax * L2E, d, 0.f);
}

// ---------------- Kernel F: fused, warp-autonomous softmax ----------------
// grid = (In/ICK, Bn/GB), 256 threads. Warp w owns b = bbase+w for ALL 1024 o's:
// per i: 32 e's in regs, single 5-shfl S-reduce, acc += e * (d/S).
// Partials written vectorized to g_part (no fp32 atomics).
__global__ void __launch_bounds__(256, 2) kfused() {
    __shared__ float4 sc2[IBR * (In / 4)];     // 4 columns = 16KB

    int t = threadIdx.x;
    int warp = t >> 5, lane = t & 31;
    int ibase = blockIdx.x * ICK;
    int b = blockIdx.y * GB + warp;

    float4 acc[8];
#pragma unroll
    for (int j = 0; j < 8; j++) acc[j] = make_float4(0.f, 0.f, 0.f, 0.f);

    const float4* bip = g_bi + (size_t)b * In + ibase;

    for (int r = 0; r < ICK / IBR; r++) {
        const float4* src = (const float4*)(g_c2_im + (size_t)(ibase + r * IBR) * In);
        __syncthreads();                        // protect overwrite of sc2
#pragma unroll
        for (int k = 0; k < 4; k++) sc2[t + 256 * k] = src[t + 256 * k];
        __syncthreads();

#pragma unroll
        for (int ii = 0; ii < IBR; ii++) {
            float4 bi = bip[r * IBR + ii];      // {g2, Bm, d, 0} broadcast load
            float g2 = bi.x, Bm = bi.y, d = bi.z;

            float4 e[8];
            float4 ps = make_float4(0.f, 0.f, 0.f, 0.f);
#pragma unroll
            for (int j = 0; j < 8; j++) {
                float4 c = sc2[ii * (In / 4) + lane + 32 * j];
                float4 ev;
                ev.x = ex2(fmaf(rsqrt_nr(fmaf(c.x, g2, EPSc)), L2E, Bm));
                ev.y = ex2(fmaf(rsqrt_nr(fmaf(c.y, g2, EPSc)), L2E, Bm));
                ev.z = ex2(fmaf(rsqrt_nr(fmaf(c.z, g2, EPSc)), L2E, Bm));
                ev.w = ex2(fmaf(rsqrt_nr(fmaf(c.w, g2, EPSc)), L2E, Bm));
                e[j] = ev;
                ps.x += ev.x; ps.y += ev.y; ps.z += ev.z; ps.w += ev.w;
            }
            float p = (ps.x + ps.y) + (ps.z + ps.w);
#pragma unroll
            for (int s = 16; s; s >>= 1) p += __shfl_xor_sync(0xffffffffu, p, s);
            float coef = __fdividef(d, p);

#pragma unroll
            for (int j = 0; j < 8; j++) {
                acc[j].x = fmaf(e[j].x, coef, acc[j].x);
                acc[j].y = fmaf(e[j].y, coef, acc[j].y);
                acc[j].z = fmaf(e[j].z, coef, acc[j].z);
                acc[j].w = fmaf(e[j].w, coef, acc[j].w);
            }
        }
    }

    float4* dst = (float4*)(g_part + ((size_t)blockIdx.x * Bn + b) * On);
#pragma unroll
    for (int j = 0; j < 8; j++) dst[lane + 32 * j] = acc[j];
}

// ---------------- Kernel R: reduce 32 partial slabs -> out ----------------
__global__ void kreduce(float* __restrict__ out) {
    int idx = blockIdx.x * 256 + threadIdx.x;   // b*On + o
    float s0 = 0.f, s1 = 0.f, s2 = 0.f, s3 = 0.f;
#pragma unroll
    for (int ib = 0; ib < NIB; ib += 4) {
        s0 += g_part[(size_t)(ib + 0) * Bn * On + idx];
        s1 += g_part[(size_t)(ib + 1) * Bn * On + idx];
        s2 += g_part[(size_t)(ib + 2) * Bn * On + idx];
        s3 += g_part[(size_t)(ib + 3) * Bn * On + idx];
    }
    out[idx] = (s0 + s1) + (s2 + s3);
}

extern "C" void kernel_launch(void* const* d_in, const int* in_sizes, int n_in,
                              void* d_out, int out_size) {
    const float* data = (const float*)d_in[0];
    const float* ix   = (const float*)d_in[1];
    const float* iy   = (const float*)d_in[2];
    const float* ox   = (const float*)d_in[3];
    const float* oy   = (const float*)d_in[4];
    const float* la   = (const float*)d_in[5];
    const float* lm   = (const float*)d_in[6];
    float* out = (float*)d_out;

    kinit<<<4, 256>>>();
    kprep<<<1024, 256>>>(ix, iy, ox, oy, la, lm);
    kg<<<(Bn * In) / 256, 256>>>(data);
    kfused<<<dim3(In / ICK, Bn / GB), 256>>>();
    kreduce<<<(Bn * On) / 256, 256>>>(out);
}

// round 8
// speedup vs baseline: 1.5533x; 1.5533x over previous
#include <cuda_runtime.h>
#include <cuda_bf16.h>
#include <float.h>

#define Bn 128
#define On 1024
#define In 1024
#define EPSc 1e-7f
#define L2E 1.4426950408889634f

#define ICK 8                  // i's per block
#define IBR 4                  // i's staged per barrier round
#define GB  8                  // b's per block (= warps)
#define NIB (In / ICK)         // 128 partial slabs

// Scratch (no allocs allowed)
__device__ float    g_c2_im[In * On];          // C^2, i-major [i][o]
__device__ unsigned g_min[In];                 // min over o of C^2[:,i]
__device__ float4   g_bi[Bn * In];             // per (b,i): {g^2, Bm=-smax*L2E, d, 0}
__device__ float    g_part[NIB * Bn * On];     // partial sums [iblk][b][o]  (64MB, fits L2)

__device__ __forceinline__ float rsq(float x) {
    float r;
    asm("rsqrt.approx.ftz.f32 %0, %1;" : "=f"(r) : "f"(x));
    return r;                                  // max rel err 2^-22.9 — sufficient (see theory)
}

__device__ __forceinline__ float ex2(float x) {
    float r;
    asm("ex2.approx.ftz.f32 %0, %1;" : "=f"(r) : "f"(x));
    return r;
}

// ---------------- init per-i min to +inf ----------------
__global__ void kinit() {
    int i = blockIdx.x * 256 + threadIdx.x;
    if (i < In) g_min[i] = 0x7F800000u;
}

// ---------------- Kernel P: C^2 transpose (o-major -> i-major) + per-i min ----
// NOTE: keeps IEEE div.rn for ix/iy, ox/oy — C is cancellation-amplified, any
// fast-div error (2e-7 abs) becomes ~0.3 nat-log error in the softmax exponent.
__global__ void kprep(const float* __restrict__ ix, const float* __restrict__ iy,
                      const float* __restrict__ ox, const float* __restrict__ oy,
                      const float* __restrict__ la, const float* __restrict__ lm) {
    __shared__ float tile[32][33];
    int tx = threadIdx.x & 31;
    int ty = threadIdx.x >> 5;
    int ob  = (blockIdx.x & 31) * 32;   // o tile base
    int ibt = (blockIdx.x >> 5) * 32;   // i tile base

#pragma unroll
    for (int k = 0; k < 4; k++) {
        int o = ob + ty + k * 8;
        int idx = o * In + ibt + tx;    // coalesced over tx (consecutive i)
        float c = (ix[idx] / iy[idx] + la[idx]) * (1.0f + lm[idx]) - ox[idx] / oy[idx];
        tile[ty + k * 8][tx] = c * c;
    }
    __syncthreads();

#pragma unroll
    for (int k = 0; k < 4; k++) {
        int il = ty + k * 8;            // local i
        float v = tile[tx][il];         // stride-33 -> conflict-free
        g_c2_im[(ibt + il) * In + ob + tx] = v;   // coalesced over tx (consecutive o)
        float mn = v;
#pragma unroll
        for (int s = 16; s; s >>= 1) mn = fminf(mn, __shfl_xor_sync(0xffffffffu, mn, s));
        if (tx == 0) atomicMin(&g_min[ibt + il], __float_as_uint(mn));
    }
}

// ---------------- Kernel G: per-(b,i) scalars {g^2, Bm, d} ----------------
// Bm only prevents overflow; any error in it cancels exactly in e/S.
__global__ void kg(const float* __restrict__ data) {
    int idx = blockIdx.x * 256 + threadIdx.x;   // b*In + i
    int i = idx & (In - 1);
    float d = data[idx];
    float g = 1.0f / (1.0f + __expf(-d));
    float g2 = g * g;
    float m2 = __uint_as_float(g_min[i]);
    float smax = rsq(fmaf(m2, g2, EPSc));
    g_bi[idx] = make_float4(g2, -smax * L2E, d, 0.f);
}

// ---------------- Kernel F: fused, warp-autonomous softmax ----------------
// grid = (In/ICK, Bn/GB), 256 threads. Warp w owns b = bbase+w for ALL 1024 o's:
// per i: 32 e's in regs, single 5-shfl S-reduce, acc += e * (d/S).
// No Newton step -> ~80 live regs, no spills.
__global__ void __launch_bounds__(256, 2) kfused() {
    __shared__ float4 sc2[IBR * (In / 4)];     // 4 columns = 16KB

    int t = threadIdx.x;
    int warp = t >> 5, lane = t & 31;
    int ibase = blockIdx.x * ICK;
    int b = blockIdx.y * GB + warp;

    float4 acc[8];
#pragma unroll
    for (int j = 0; j < 8; j++) acc[j] = make_float4(0.f, 0.f, 0.f, 0.f);

    const float4* bip = g_bi + (size_t)b * In + ibase;

    for (int r = 0; r < ICK / IBR; r++) {
        const float4* src = (const float4*)(g_c2_im + (size_t)(ibase + r * IBR) * In);
        __syncthreads();                        // protect overwrite of sc2
#pragma unroll
        for (int k = 0; k < 4; k++) sc2[t + 256 * k] = src[t + 256 * k];
        __syncthreads();

#pragma unroll
        for (int ii = 0; ii < IBR; ii++) {
            float4 bi = bip[r * IBR + ii];      // {g2, Bm, d, 0} broadcast load
            float g2 = bi.x, Bm = bi.y, d = bi.z;

            float4 e[8];
            float4 ps = make_float4(0.f, 0.f, 0.f, 0.f);
#pragma unroll
            for (int j = 0; j < 8; j++) {
                float4 c = sc2[ii * (In / 4) + lane + 32 * j];
                float4 ev;
                ev.x = ex2(fmaf(rsq(fmaf(c.x, g2, EPSc)), L2E, Bm));
                ev.y = ex2(fmaf(rsq(fmaf(c.y, g2, EPSc)), L2E, Bm));
                ev.z = ex2(fmaf(rsq(fmaf(c.z, g2, EPSc)), L2E, Bm));
                ev.w = ex2(fmaf(rsq(fmaf(c.w, g2, EPSc)), L2E, Bm));
                e[j] = ev;
                ps.x += ev.x; ps.y += ev.y; ps.z += ev.z; ps.w += ev.w;
            }
            float p = (ps.x + ps.y) + (ps.z + ps.w);
#pragma unroll
            for (int s = 16; s; s >>= 1) p += __shfl_xor_sync(0xffffffffu, p, s);
            float coef = __fdividef(d, p);

#pragma unroll
            for (int j = 0; j < 8; j++) {
                acc[j].x = fmaf(e[j].x, coef, acc[j].x);
                acc[j].y = fmaf(e[j].y, coef, acc[j].y);
                acc[j].z = fmaf(e[j].z, coef, acc[j].z);
                acc[j].w = fmaf(e[j].w, coef, acc[j].w);
            }
        }
    }

    float4* dst = (float4*)(g_part + ((size_t)blockIdx.x * Bn + b) * On);
#pragma unroll
    for (int j = 0; j < 8; j++) dst[lane + 32 * j] = acc[j];
}

// ---------------- Kernel R: reduce 128 partial slabs -> out ----------------
__global__ void kreduce(float* __restrict__ out) {
    int idx = blockIdx.x * 256 + threadIdx.x;   // b*On + o
    float s0 = 0.f, s1 = 0.f, s2 = 0.f, s3 = 0.f;
#pragma unroll 8
    for (int ib = 0; ib < NIB; ib += 4) {
        s0 += g_part[(size_t)(ib + 0) * Bn * On + idx];
        s1 += g_part[(size_t)(ib + 1) * Bn * On + idx];
        s2 += g_part[(size_t)(ib + 2) * Bn * On + idx];
        s3 += g_part[(size_t)(ib + 3) * Bn * On + idx];
    }
    out[idx] = (s0 + s1) + (s2 + s3);
}

extern "C" void kernel_launch(void* const* d_in, const int* in_sizes, int n_in,
                              void* d_out, int out_size) {
    const float* data = (const float*)d_in[0];
    const float* ix   = (const float*)d_in[1];
    const float* iy   = (const float*)d_in[2];
    const float* ox   = (const float*)d_in[3];
    const float* oy   = (const float*)d_in[4];
    const float* la   = (const float*)d_in[5];
    const float* lm   = (const float*)d_in[6];
    float* out = (float*)d_out;

    kinit<<<4, 256>>>();
    kprep<<<1024, 256>>>(ix, iy, ox, oy, la, lm);
    kg<<<(Bn * In) / 256, 256>>>(data);
    kfused<<<dim3(In / ICK, Bn / GB), 256>>>();
    kreduce<<<(Bn * On) / 256, 256>>>(out);
}

// round 9
// speedup vs baseline: 9.3129x; 5.9955x over previous
#include <cuda_runtime.h>
#include <cuda_bf16.h>
#include <float.h>

#define Bn 128
#define On 1024
#define In 1024
#define EPSc 1e-7f
#define L2E 1.4426950408889634f
#define CUT_NATS 20.794415417f   // 30 * ln(2): drop terms with weight < 2^-30

// Scratch (no allocs allowed)
__device__ float g_c2_im[In * On];   // C^2, i-major [i][o]

__device__ __forceinline__ float rsq(float x) {
    float r;
    asm("rsqrt.approx.ftz.f32 %0, %1;" : "=f"(r) : "f"(x));
    return r;
}
__device__ __forceinline__ float ex2(float x) {
    float r;
    asm("ex2.approx.ftz.f32 %0, %1;" : "=f"(r) : "f"(x));
    return r;
}

// ---------------- Kernel P: C^2 transpose (o-major inputs -> i-major) ----------------
// Keeps IEEE div.rn for ix/iy, ox/oy — C is cancellation-amplified; fast-div
// error would shift the softmax exponent by O(0.1) nats.
__global__ void kprep(const float* __restrict__ ix, const float* __restrict__ iy,
                      const float* __restrict__ ox, const float* __restrict__ oy,
                      const float* __restrict__ la, const float* __restrict__ lm) {
    __shared__ float tile[32][33];
    int tx = threadIdx.x & 31;
    int ty = threadIdx.x >> 5;
    int ob  = (blockIdx.x & 31) * 32;   // o tile base
    int ibt = (blockIdx.x >> 5) * 32;   // i tile base

#pragma unroll
    for (int k = 0; k < 4; k++) {
        int o = ob + ty + k * 8;
        int idx = o * In + ibt + tx;    // coalesced over tx (consecutive i)
        float c = (ix[idx] / iy[idx] + la[idx]) * (1.0f + lm[idx]) - ox[idx] / oy[idx];
        tile[ty + k * 8][tx] = c * c;
    }
    __syncthreads();

#pragma unroll
    for (int k = 0; k < 4; k++) {
        int il = ty + k * 8;            // local i
        g_c2_im[(ibt + il) * In + ob + tx] = tile[tx][il];  // coalesced (consecutive o)
    }
}

// ---------------- Kernel M: per-i sparse softmax ----------------
// Block per i, 256 threads.
//   1) stage C^2[:,i] (4KB) in SMEM, block-min -> c2min
//   2) threads t<128 (b=t): g2, Bm, d; per-(b,i) keep-threshold on C^2;
//      block-max -> T(i)  (conservative superset of contributors for all b)
//   3) compact {o : C^2 <= T} into SMEM list
//   4) each b: S over candidates (exact), then atomicAdd (d/S)*e into out
__global__ void __launch_bounds__(256, 4) kmega(const float* __restrict__ data,
                                                float* __restrict__ out) {
    __shared__ float sc2[In];       // 4KB
    __shared__ int   slist[In];     // 4KB (worst case all kept)
    __shared__ float sred[8];
    __shared__ float sbcast[2];     // {c2min, T}
    __shared__ int   scnt;

    int i = blockIdx.x;
    int t = threadIdx.x;
    int lane = t & 31, warp = t >> 5;

    if (t == 0) scnt = 0;

    // --- stage row + min ---
    float4 v = ((const float4*)(g_c2_im + (size_t)i * In))[t];
    ((float4*)sc2)[t] = v;
    float mn = fminf(fminf(v.x, v.y), fminf(v.z, v.w));
#pragma unroll
    for (int s = 16; s; s >>= 1) mn = fminf(mn, __shfl_xor_sync(0xffffffffu, mn, s));
    if (lane == 0) sred[warp] = mn;
    __syncthreads();
    if (t == 0) {
        float m = sred[0];
#pragma unroll
        for (int w = 1; w < 8; w++) m = fminf(m, sred[w]);
        sbcast[0] = m;
    }
    __syncthreads();
    float c2min = sbcast[0];

    // --- per-b scalars + keep threshold ---
    float g2 = 0.f, Bm = 0.f, d = 0.f, keep = 0.f;
    if (t < Bn) {
        d = data[t * In + i];
        float g = 1.0f / (1.0f + __expf(-d));
        g2 = g * g;
        float smax = rsq(fmaf(c2min, g2, EPSc));
        Bm = -smax * L2E;
        float q = smax - CUT_NATS;
        if (q > 0.f) {
            float iq2 = 1.0f / (q * q);          // strictly > g2*c2min + eps (1.3% margin)
            keep = (iq2 - EPSc) / g2;
        } else {
            keep = FLT_MAX;                       // broad-softmax guard: keep everything
        }
    }
    float kx = keep;
#pragma unroll
    for (int s = 16; s; s >>= 1) kx = fmaxf(kx, __shfl_xor_sync(0xffffffffu, kx, s));
    __syncthreads();                              // sred reuse: min phase fully read
    if (lane == 0 && warp < 4) sred[warp] = kx;
    __syncthreads();
    if (t == 0) sbcast[1] = fmaxf(fmaxf(sred[0], sred[1]), fmaxf(sred[2], sred[3]));
    __syncthreads();
    float T = sbcast[1];

    // --- compact candidates ---
#pragma unroll
    for (int j = 0; j < 4; j++) {
        int o = t + 256 * j;
        if (sc2[o] <= T) {
            int p = atomicAdd(&scnt, 1);
            slist[p] = o;
        }
    }
    __syncthreads();
    int cnt = scnt;

    // --- evaluate candidates exactly, accumulate output ---
    if (t < Bn) {
        float S = 0.f;
        for (int k = 0; k < cnt; k++) {
            float c2 = sc2[slist[k]];
            S += ex2(fmaf(rsq(fmaf(c2, g2, EPSc)), L2E, Bm));
        }
        float coef = __fdividef(d, S);
        float* ob = out + t * On;
        for (int k = 0; k < cnt; k++) {
            int o = slist[k];
            float e = ex2(fmaf(rsq(fmaf(sc2[o], g2, EPSc)), L2E, Bm));
            atomicAdd(ob + o, coef * e);
        }
    }
}

extern "C" void kernel_launch(void* const* d_in, const int* in_sizes, int n_in,
                              void* d_out, int out_size) {
    const float* data = (const float*)d_in[0];
    const float* ix   = (const float*)d_in[1];
    const float* iy   = (const float*)d_in[2];
    const float* ox   = (const float*)d_in[3];
    const float* oy   = (const float*)d_in[4];
    const float* la   = (const float*)d_in[5];
    const float* lm   = (const float*)d_in[6];
    float* out = (float*)d_out;

    cudaMemsetAsync(out, 0, (size_t)out_size * sizeof(float));
    kprep<<<1024, 256>>>(ix, iy, ox, oy, la, lm);
    kmega<<<In, 256>>>(data, out);
}